// round 1
// baseline (speedup 1.0000x reference)
#include <cuda_runtime.h>
#include <cstdint>

#define E_DIM 1024
#define HEADS 16
#define HDIM  64
#define SEQ   2048
#define BATCH 4
#define MTOT  (BATCH*SEQ)   // 8192

// Scratch (alloc-free rule: __device__ globals)
__device__ float g_q[MTOT*E_DIM];
__device__ float g_k[MTOT*E_DIM];
__device__ float g_v[MTOT*E_DIM];
__device__ float g_attn[MTOT*E_DIM];

__device__ __forceinline__ uint32_t f2tf(float f){
    uint32_t u; asm("cvt.rna.tf32.f32 %0, %1;" : "=r"(u) : "f"(f)); return u;
}

__device__ __forceinline__ void mma_tf32(float& c0, float& c1, float& c2, float& c3,
    uint32_t a0, uint32_t a1, uint32_t a2, uint32_t a3, uint32_t b0, uint32_t b1){
    asm volatile(
        "mma.sync.aligned.m16n8k8.row.col.f32.tf32.tf32.f32 "
        "{%0,%1,%2,%3},{%4,%5,%6,%7},{%8,%9},{%0,%1,%2,%3};"
        : "+f"(c0), "+f"(c1), "+f"(c2), "+f"(c3)
        : "r"(a0), "r"(a1), "r"(a2), "r"(a3), "r"(b0), "r"(b1));
}

// ============================================================================
// GEMM: C[M,N] = A[M,K] @ B[N,K]^T   (x @ W.T), all row-major fp32, tf32 mma
// BM=128, BN=128, BK=16, 256 threads (8 warps: 2 m-groups x 4 n-groups)
// ============================================================================
#define BM 128
#define BN 128
#define BK 16
#define KPAD 20   // stride 20 -> row bank bases are distinct multiples of 4: conflict-free frag loads

__global__ __launch_bounds__(256)
void gemm_xwt(const float* __restrict__ A, const float* __restrict__ B,
              float* __restrict__ C, int M, int N, int K)
{
    __shared__ uint32_t As[BM][KPAD];
    __shared__ uint32_t Bs[BN][KPAD];

    const int t = threadIdx.x;
    const int w = t >> 5, lane = t & 31;
    const int wm = w & 1;      // 64-row half
    const int wn = w >> 1;     // 32-col quarter
    const int bm = blockIdx.y * BM, bn = blockIdx.x * BN;

    float acc[4][4][4];
    #pragma unroll
    for (int i = 0; i < 4; i++)
        #pragma unroll
        for (int j = 0; j < 4; j++)
            #pragma unroll
            for (int r = 0; r < 4; r++) acc[i][j][r] = 0.f;

    for (int k0 = 0; k0 < K; k0 += BK) {
        // load 128x16 tiles of A and B, converting to tf32 (rna)
        #pragma unroll
        for (int i = 0; i < 2; i++) {
            int lin = t + i * 256;
            int row = lin >> 2, c4 = (lin & 3) * 4;
            float4 va = *(const float4*)(A + (size_t)(bm + row) * K + k0 + c4);
            As[row][c4+0] = f2tf(va.x); As[row][c4+1] = f2tf(va.y);
            As[row][c4+2] = f2tf(va.z); As[row][c4+3] = f2tf(va.w);
            float4 vb = *(const float4*)(B + (size_t)(bn + row) * K + k0 + c4);
            Bs[row][c4+0] = f2tf(vb.x); Bs[row][c4+1] = f2tf(vb.y);
            Bs[row][c4+2] = f2tf(vb.z); Bs[row][c4+3] = f2tf(vb.w);
        }
        __syncthreads();

        #pragma unroll
        for (int kk = 0; kk < BK; kk += 8) {
            uint32_t af[4][4], bf[4][2];
            #pragma unroll
            for (int mt = 0; mt < 4; mt++) {
                int r = wm * 64 + mt * 16 + (lane >> 2);
                int c = kk + (lane & 3);
                af[mt][0] = As[r][c];     af[mt][1] = As[r+8][c];
                af[mt][2] = As[r][c+4];   af[mt][3] = As[r+8][c+4];
            }
            #pragma unroll
            for (int nt = 0; nt < 4; nt++) {
                int n = wn * 32 + nt * 8 + (lane >> 2);
                int c = kk + (lane & 3);
                bf[nt][0] = Bs[n][c];     bf[nt][1] = Bs[n][c+4];
            }
            #pragma unroll
            for (int mt = 0; mt < 4; mt++)
                #pragma unroll
                for (int nt = 0; nt < 4; nt++)
                    mma_tf32(acc[mt][nt][0], acc[mt][nt][1], acc[mt][nt][2], acc[mt][nt][3],
                             af[mt][0], af[mt][1], af[mt][2], af[mt][3],
                             bf[nt][0], bf[nt][1]);
        }
        __syncthreads();
    }

    #pragma unroll
    for (int mt = 0; mt < 4; mt++) {
        int r0 = bm + wm * 64 + mt * 16 + (lane >> 2);
        #pragma unroll
        for (int nt = 0; nt < 4; nt++) {
            int cc = bn + wn * 32 + nt * 8 + (lane & 3) * 2;
            *(float2*)(C + (size_t)r0 * N + cc)      = make_float2(acc[mt][nt][0], acc[mt][nt][1]);
            *(float2*)(C + (size_t)(r0+8) * N + cc)  = make_float2(acc[mt][nt][2], acc[mt][nt][3]);
        }
    }
}

// ============================================================================
// Flash attention: per-CTA one (b, h, 64-row q-tile). Br=Bc=64, D=64.
// 256 threads = 8 warps: 2 m-halves (32 rows) x 4 n-quarters (16 cols).
// TF32 mma for QK^T and PV; online softmax via smem S-tile round trip.
// ============================================================================
#define DPAD 68
#define SMEM_ATTN ((4*64*DPAD + 3*64) * 4)

__global__ __launch_bounds__(256)
void flash_attn(const float* __restrict__ Q, const float* __restrict__ K,
                const float* __restrict__ V, float* __restrict__ O)
{
    extern __shared__ float sm[];
    float* Qs   = sm;                 // [64][DPAD] tf32 bits
    float* Ks   = Qs + 64 * DPAD;     // [64][DPAD] tf32 bits (row = key, col = d)
    float* Vs   = Ks + 64 * DPAD;     // [64][DPAD] tf32 bits TRANSPOSED: [d][s]
    float* Ss   = Vs + 64 * DPAD;     // [64][DPAD] scores (fp32) -> P (tf32 bits)
    float* mrow = Ss + 64 * DPAD;     // [64]
    float* lrow = mrow + 64;          // [64]
    float* arow = lrow + 64;          // [64]

    const int t = threadIdx.x, w = t >> 5, lane = t & 31;
    const int wm = w & 1;     // 32-row half
    const int wn = w >> 1;    // 16-col quarter
    const int qt = blockIdx.x, h = blockIdx.y, b = blockIdx.z;

    const size_t base = (size_t)b * SEQ * E_DIM + (size_t)h * HDIM;
    const float* Qg = Q + base + (size_t)(qt * 64) * E_DIM;
    const float* Kg = K + base;
    const float* Vg = V + base;

    uint32_t* Qu = (uint32_t*)Qs;
    uint32_t* Ku = (uint32_t*)Ks;
    uint32_t* Vu = (uint32_t*)Vs;
    uint32_t* Su = (uint32_t*)Ss;

    // Load Q tile (scaled by sm_scale = 1/sqrt(64) = 0.125), convert to tf32
    #pragma unroll
    for (int i = 0; i < 4; i++) {
        int lin = t + i * 256;
        int row = lin >> 4, c4 = (lin & 15) * 4;
        float4 v = *(const float4*)(Qg + (size_t)row * E_DIM + c4);
        uint32_t* dst = &Qu[row * DPAD + c4];
        dst[0] = f2tf(v.x * 0.125f); dst[1] = f2tf(v.y * 0.125f);
        dst[2] = f2tf(v.z * 0.125f); dst[3] = f2tf(v.w * 0.125f);
    }
    if (t < 64) { mrow[t] = -1e30f; lrow[t] = 0.f; }

    float o[2][2][4];
    #pragma unroll
    for (int i = 0; i < 2; i++)
        #pragma unroll
        for (int j = 0; j < 2; j++)
            #pragma unroll
            for (int r = 0; r < 4; r++) o[i][j][r] = 0.f;
    __syncthreads();

    for (int kt = 0; kt < SEQ / 64; kt++) {
        const float* Kt = Kg + (size_t)(kt * 64) * E_DIM;
        const float* Vt = Vg + (size_t)(kt * 64) * E_DIM;

        // Load K (natural) and V (transposed) tiles, tf32-convert
        #pragma unroll
        for (int i = 0; i < 4; i++) {
            int lin = t + i * 256;
            int row = lin >> 4, c4 = (lin & 15) * 4;
            float4 kv = *(const float4*)(Kt + (size_t)row * E_DIM + c4);
            uint32_t* kd = &Ku[row * DPAD + c4];
            kd[0] = f2tf(kv.x); kd[1] = f2tf(kv.y); kd[2] = f2tf(kv.z); kd[3] = f2tf(kv.w);
            float4 vv = *(const float4*)(Vt + (size_t)row * E_DIM + c4);
            Vu[(c4+0) * DPAD + row] = f2tf(vv.x);
            Vu[(c4+1) * DPAD + row] = f2tf(vv.y);
            Vu[(c4+2) * DPAD + row] = f2tf(vv.z);
            Vu[(c4+3) * DPAD + row] = f2tf(vv.w);
        }
        __syncthreads();

        // ---- S = Q @ K^T (64x64), each warp computes 32x16 ----
        float sc[2][2][4];
        #pragma unroll
        for (int i = 0; i < 2; i++)
            #pragma unroll
            for (int j = 0; j < 2; j++)
                #pragma unroll
                for (int r = 0; r < 4; r++) sc[i][j][r] = 0.f;

        #pragma unroll
        for (int kk = 0; kk < 64; kk += 8) {
            uint32_t af[2][4], bf[2][2];
            #pragma unroll
            for (int mt = 0; mt < 2; mt++) {
                int r = wm * 32 + mt * 16 + (lane >> 2);
                int c = kk + (lane & 3);
                af[mt][0] = Qu[r * DPAD + c];      af[mt][1] = Qu[(r+8) * DPAD + c];
                af[mt][2] = Qu[r * DPAD + c + 4];  af[mt][3] = Qu[(r+8) * DPAD + c + 4];
            }
            #pragma unroll
            for (int nt = 0; nt < 2; nt++) {
                int n = wn * 16 + nt * 8 + (lane >> 2);
                int c = kk + (lane & 3);
                bf[nt][0] = Ku[n * DPAD + c]; bf[nt][1] = Ku[n * DPAD + c + 4];
            }
            #pragma unroll
            for (int mt = 0; mt < 2; mt++)
                #pragma unroll
                for (int nt = 0; nt < 2; nt++)
                    mma_tf32(sc[mt][nt][0], sc[mt][nt][1], sc[mt][nt][2], sc[mt][nt][3],
                             af[mt][0], af[mt][1], af[mt][2], af[mt][3],
                             bf[nt][0], bf[nt][1]);
        }
        // store S tile to smem (fp32)
        #pragma unroll
        for (int mt = 0; mt < 2; mt++) {
            int r = wm * 32 + mt * 16 + (lane >> 2);
            #pragma unroll
            for (int nt = 0; nt < 2; nt++) {
                int c = wn * 16 + nt * 8 + (lane & 3) * 2;
                *(float2*)&Ss[r * DPAD + c]       = make_float2(sc[mt][nt][0], sc[mt][nt][1]);
                *(float2*)&Ss[(r+8) * DPAD + c]   = make_float2(sc[mt][nt][2], sc[mt][nt][3]);
            }
        }
        __syncthreads();

        // ---- online softmax: 4 threads per row, 16 cols each ----
        {
            int row = t >> 2;
            float* srow = &Ss[row * DPAD + (t & 3) * 16];
            float mx = -1e30f;
            #pragma unroll
            for (int j = 0; j < 16; j++) mx = fmaxf(mx, srow[j]);
            mx = fmaxf(mx, __shfl_xor_sync(0xffffffffu, mx, 1));
            mx = fmaxf(mx, __shfl_xor_sync(0xffffffffu, mx, 2));
            float mprev = mrow[row];
            float mnew  = fmaxf(mprev, mx);
            float sum = 0.f;
            #pragma unroll
            for (int j = 0; j < 16; j++) {
                float p = __expf(srow[j] - mnew);
                sum += p;
                ((uint32_t*)srow)[j] = f2tf(p);   // P in tf32 for next mma
            }
            sum += __shfl_xor_sync(0xffffffffu, sum, 1);
            sum += __shfl_xor_sync(0xffffffffu, sum, 2);
            if ((t & 3) == 0) {
                float al = __expf(mprev - mnew);
                arow[row] = al;
                lrow[row] = lrow[row] * al + sum;
                mrow[row] = mnew;
            }
        }
        __syncthreads();

        // ---- rescale O, then O += P @ V ----
        #pragma unroll
        for (int mt = 0; mt < 2; mt++) {
            int r0 = wm * 32 + mt * 16 + (lane >> 2);
            float a0 = arow[r0], a1 = arow[r0 + 8];
            #pragma unroll
            for (int nt = 0; nt < 2; nt++) {
                o[mt][nt][0] *= a0; o[mt][nt][1] *= a0;
                o[mt][nt][2] *= a1; o[mt][nt][3] *= a1;
            }
        }
        #pragma unroll
        for (int kk = 0; kk < 64; kk += 8) {
            uint32_t af[2][4], bf[2][2];
            #pragma unroll
            for (int mt = 0; mt < 2; mt++) {
                int r = wm * 32 + mt * 16 + (lane >> 2);
                int c = kk + (lane & 3);
                af[mt][0] = Su[r * DPAD + c];      af[mt][1] = Su[(r+8) * DPAD + c];
                af[mt][2] = Su[r * DPAD + c + 4];  af[mt][3] = Su[(r+8) * DPAD + c + 4];
            }
            #pragma unroll
            for (int nt = 0; nt < 2; nt++) {
                int n = wn * 16 + nt * 8 + (lane >> 2);    // d index
                int c = kk + (lane & 3);                   // s index
                bf[nt][0] = Vu[n * DPAD + c]; bf[nt][1] = Vu[n * DPAD + c + 4];
            }
            #pragma unroll
            for (int mt = 0; mt < 2; mt++)
                #pragma unroll
                for (int nt = 0; nt < 2; nt++)
                    mma_tf32(o[mt][nt][0], o[mt][nt][1], o[mt][nt][2], o[mt][nt][3],
                             af[mt][0], af[mt][1], af[mt][2], af[mt][3],
                             bf[nt][0], bf[nt][1]);
        }
        __syncthreads();
    }

    // epilogue: divide by l, write [b*S + q, h*64 + d]
    float* Og = O + ((size_t)b * SEQ + qt * 64) * E_DIM + (size_t)h * HDIM;
    #pragma unroll
    for (int mt = 0; mt < 2; mt++) {
        int r0 = wm * 32 + mt * 16 + (lane >> 2);
        float inv0 = 1.f / lrow[r0], inv1 = 1.f / lrow[r0 + 8];
        #pragma unroll
        for (int nt = 0; nt < 2; nt++) {
            int c = wn * 16 + nt * 8 + (lane & 3) * 2;
            *(float2*)(Og + (size_t)r0 * E_DIM + c)     = make_float2(o[mt][nt][0] * inv0, o[mt][nt][1] * inv0);
            *(float2*)(Og + (size_t)(r0+8) * E_DIM + c) = make_float2(o[mt][nt][2] * inv1, o[mt][nt][3] * inv1);
        }
    }
}

// ============================================================================
extern "C" void kernel_launch(void* const* d_in, const int* in_sizes, int n_in,
                              void* d_out, int out_size)
{
    const float* query = (const float*)d_in[0];
    const float* key   = (const float*)d_in[1];
    const float* value = (const float*)d_in[2];
    const float* Wq    = (const float*)d_in[3];
    const float* Wk    = (const float*)d_in[4];
    const float* Wv    = (const float*)d_in[5];
    const float* Wo    = (const float*)d_in[6];
    float* out = (float*)d_out;

    float *gq, *gk, *gv, *ga;
    cudaGetSymbolAddress((void**)&gq, g_q);
    cudaGetSymbolAddress((void**)&gk, g_k);
    cudaGetSymbolAddress((void**)&gv, g_v);
    cudaGetSymbolAddress((void**)&ga, g_attn);

    cudaFuncSetAttribute(flash_attn, cudaFuncAttributeMaxDynamicSharedMemorySize, SMEM_ATTN);

    dim3 gb(E_DIM / BN, MTOT / BM);   // (8, 64)
    gemm_xwt<<<gb, 256>>>(query, Wq, gq, MTOT, E_DIM, E_DIM);
    gemm_xwt<<<gb, 256>>>(key,   Wk, gk, MTOT, E_DIM, E_DIM);
    gemm_xwt<<<gb, 256>>>(value, Wv, gv, MTOT, E_DIM, E_DIM);

    flash_attn<<<dim3(SEQ / 64, HEADS, BATCH), 256, SMEM_ATTN>>>(gq, gk, gv, ga);

    gemm_xwt<<<gb, 256>>>(ga, Wo, out, MTOT, E_DIM, E_DIM);
}

// round 2
// speedup vs baseline: 1.6537x; 1.6537x over previous
#include <cuda_runtime.h>
#include <cstdint>

#define E_DIM 1024
#define HEADS 16
#define HDIM  64
#define SEQ   2048
#define BATCH 4
#define MTOT  (BATCH*SEQ)   // 8192

// Scratch (alloc-free rule: __device__ globals)
__device__ float g_q[MTOT*E_DIM];
__device__ float g_k[MTOT*E_DIM];
__device__ float g_v[MTOT*E_DIM];
__device__ float g_attn[MTOT*E_DIM];

__device__ __forceinline__ uint32_t f2tf(float f){
    uint32_t u; asm("cvt.rna.tf32.f32 %0, %1;" : "=r"(u) : "f"(f)); return u;
}
__device__ __forceinline__ float exp2a(float x){
    float r; asm("ex2.approx.f32 %0, %1;" : "=f"(r) : "f"(x)); return r;
}

__device__ __forceinline__ void mma_tf32(float& c0, float& c1, float& c2, float& c3,
    uint32_t a0, uint32_t a1, uint32_t a2, uint32_t a3, uint32_t b0, uint32_t b1){
    asm volatile(
        "mma.sync.aligned.m16n8k8.row.col.f32.tf32.tf32.f32 "
        "{%0,%1,%2,%3},{%4,%5,%6,%7},{%8,%9},{%0,%1,%2,%3};"
        : "+f"(c0), "+f"(c1), "+f"(c2), "+f"(c3)
        : "r"(a0), "r"(a1), "r"(a2), "r"(a3), "r"(b0), "r"(b1));
}

__device__ __forceinline__ void cpa16(uint32_t dst, const void* src){
    asm volatile("cp.async.cg.shared.global [%0], [%1], 16;" :: "r"(dst), "l"(src));
}

// ============================================================================
// GEMM: C[M,N] = A[M,K] @ B[N,K]^T, tf32 mma, cp.async double-buffered.
// BM=BN=128, BK=16, 256 threads. blockIdx.z selects among 3 (A,W,C) triples
// so the QKV projections run as ONE launch.
// ============================================================================
#define BM 128
#define BN 128
#define BK 16
#define KPAD 20

__global__ __launch_bounds__(256)
void gemm3(const float* __restrict__ A0, const float* __restrict__ A1, const float* __restrict__ A2,
           const float* __restrict__ W0, const float* __restrict__ W1, const float* __restrict__ W2,
           float* __restrict__ C0, float* __restrict__ C1, float* __restrict__ C2)
{
    __shared__ alignas(16) float As[2][BM][KPAD];
    __shared__ alignas(16) float Bs[2][BM][KPAD];

    const float* A = blockIdx.z == 0 ? A0 : (blockIdx.z == 1 ? A1 : A2);
    const float* B = blockIdx.z == 0 ? W0 : (blockIdx.z == 1 ? W1 : W2);
    float*       C = blockIdx.z == 0 ? C0 : (blockIdx.z == 1 ? C1 : C2);
    const int K = E_DIM, N = E_DIM;

    const int t = threadIdx.x;
    const int w = t >> 5, lane = t & 31;
    const int wm = w & 1;       // 64-row half
    const int wn = w >> 1;      // 32-col quarter
    const int rr = lane >> 2, qq = lane & 3;
    const int bm = blockIdx.y * BM, bn = blockIdx.x * BN;

    // cp.async tile-fill mapping: each thread copies 2 rows x 16B per matrix
    const int ldrow0 = t >> 2, ldc4 = (t & 3) * 4;
    const int ldrow1 = ldrow0 + 64;
    const uint32_t sAb = (uint32_t)__cvta_generic_to_shared(&As[0][0][0]);
    const uint32_t sBb = (uint32_t)__cvta_generic_to_shared(&Bs[0][0][0]);

    auto issue = [&](int k0, int s){
        cpa16(sAb + (uint32_t)(((s*BM + ldrow0)*KPAD + ldc4)*4), A + (size_t)(bm + ldrow0)*K + k0 + ldc4);
        cpa16(sAb + (uint32_t)(((s*BM + ldrow1)*KPAD + ldc4)*4), A + (size_t)(bm + ldrow1)*K + k0 + ldc4);
        cpa16(sBb + (uint32_t)(((s*BM + ldrow0)*KPAD + ldc4)*4), B + (size_t)(bn + ldrow0)*K + k0 + ldc4);
        cpa16(sBb + (uint32_t)(((s*BM + ldrow1)*KPAD + ldc4)*4), B + (size_t)(bn + ldrow1)*K + k0 + ldc4);
    };

    float acc[4][4][4];
    #pragma unroll
    for (int i = 0; i < 4; i++)
        #pragma unroll
        for (int j = 0; j < 4; j++)
            #pragma unroll
            for (int r2 = 0; r2 < 4; r2++) acc[i][j][r2] = 0.f;

    const int NKI = K / BK;   // 64
    issue(0, 0);
    asm volatile("cp.async.commit_group;");

    for (int ki = 0; ki < NKI; ki++) {
        if (ki + 1 < NKI) {
            issue((ki+1)*BK, (ki+1)&1);
            asm volatile("cp.async.commit_group;");
            asm volatile("cp.async.wait_group 1;");
        } else {
            asm volatile("cp.async.wait_group 0;");
        }
        __syncthreads();
        const int s = ki & 1;

        #pragma unroll
        for (int kk = 0; kk < BK; kk += 8) {
            uint32_t af[4][4], bf[4][2];
            #pragma unroll
            for (int mt = 0; mt < 4; mt++) {
                int r = wm * 64 + mt * 16 + rr;
                int c = kk + qq;
                af[mt][0] = f2tf(As[s][r][c]);     af[mt][1] = f2tf(As[s][r+8][c]);
                af[mt][2] = f2tf(As[s][r][c+4]);   af[mt][3] = f2tf(As[s][r+8][c+4]);
            }
            #pragma unroll
            for (int nt = 0; nt < 4; nt++) {
                int n = wn * 32 + nt * 8 + rr;
                int c = kk + qq;
                bf[nt][0] = f2tf(Bs[s][n][c]);     bf[nt][1] = f2tf(Bs[s][n][c+4]);
            }
            #pragma unroll
            for (int mt = 0; mt < 4; mt++)
                #pragma unroll
                for (int nt = 0; nt < 4; nt++)
                    mma_tf32(acc[mt][nt][0], acc[mt][nt][1], acc[mt][nt][2], acc[mt][nt][3],
                             af[mt][0], af[mt][1], af[mt][2], af[mt][3],
                             bf[nt][0], bf[nt][1]);
        }
        __syncthreads();
    }

    #pragma unroll
    for (int mt = 0; mt < 4; mt++) {
        int r0 = bm + wm * 64 + mt * 16 + rr;
        #pragma unroll
        for (int nt = 0; nt < 4; nt++) {
            int cc = bn + wn * 32 + nt * 8 + qq * 2;
            *(float2*)(C + (size_t)r0 * N + cc)      = make_float2(acc[mt][nt][0], acc[mt][nt][1]);
            *(float2*)(C + (size_t)(r0+8) * N + cc)  = make_float2(acc[mt][nt][2], acc[mt][nt][3]);
        }
    }
}

// ============================================================================
// Flash attention v2: register-resident softmax.
// Br=128, Bc=64. 8 warps; warp w owns rows [16w, 16w+16) => full S rows live
// in one warp => softmax entirely via quad shfl. No S smem round trip,
// no V transpose, no stats smem. Q/K stored k-pair-permuted for LDS.64 frags.
//   permuted position of col c within its 8-group: 2*(c&3) + ((c&4)>>2)
// ============================================================================
#define SPAD 72
#define FLASH_SMEM ((128 + 64 + 64) * SPAD * 4)   // 73728 bytes

__global__ __launch_bounds__(256)
void flash_attn(const float* __restrict__ Q, const float* __restrict__ K,
                const float* __restrict__ V, float* __restrict__ O)
{
    extern __shared__ uint32_t sm[];
    uint32_t* Qs = sm;              // [128][SPAD] permuted tf32
    uint32_t* Ks = Qs + 128*SPAD;   // [64][SPAD]  permuted tf32
    uint32_t* Vs = Ks + 64*SPAD;    // [64][SPAD]  natural tf32  (row=s, col=d)

    const int t = threadIdx.x, w = t >> 5, lane = t & 31;
    const int q = lane & 3, r = lane >> 2;
    const int R0 = w * 16 + r, R1 = R0 + 8;
    const int qt = blockIdx.x, h = blockIdx.y, b = blockIdx.z;

    const size_t base = (size_t)b * SEQ * E_DIM + (size_t)h * HDIM;
    const float* Qg = Q + base + (size_t)(qt * 128) * E_DIM;
    const float* Kg = K + base;
    const float* Vg = V + base;

    const float qscale = 0.125f * 1.4426950408889634f;   // sm_scale * log2(e)

    // ---- load Q tile once (permuted, tf32, pre-scaled) ----
    #pragma unroll
    for (int i = 0; i < 8; i++) {
        int lin = t + i * 256;
        int row = lin >> 4, c4 = (lin & 15) * 4;
        float4 v = *(const float4*)(Qg + (size_t)row * E_DIM + c4);
        uint32_t* dst = &Qs[row * SPAD + (c4 & ~7) + ((c4 & 4) >> 2)];
        dst[0] = f2tf(v.x * qscale); dst[2] = f2tf(v.y * qscale);
        dst[4] = f2tf(v.z * qscale); dst[6] = f2tf(v.w * qscale);
    }

    float of[8][4];
    #pragma unroll
    for (int nt = 0; nt < 8; nt++)
        #pragma unroll
        for (int e = 0; e < 4; e++) of[nt][e] = 0.f;
    float m0 = -1e30f, m1 = -1e30f, l0 = 0.f, l1 = 0.f;

    const int srcA = (lane & ~3) | (q >> 1);
    const int srcB = srcA + 2;

    for (int kt = 0; kt < SEQ / 64; kt++) {
        __syncthreads();   // previous iter's readers done before overwrite
        // ---- fill K (permuted) and V (natural) ----
        #pragma unroll
        for (int i = 0; i < 4; i++) {
            int lin = t + i * 256;
            int row = lin >> 4, c4 = (lin & 15) * 4;
            float4 kv = *(const float4*)(Kg + (size_t)(kt*64 + row) * E_DIM + c4);
            uint32_t* kd = &Ks[row * SPAD + (c4 & ~7) + ((c4 & 4) >> 2)];
            kd[0] = f2tf(kv.x); kd[2] = f2tf(kv.y); kd[4] = f2tf(kv.z); kd[6] = f2tf(kv.w);
            float4 vv = *(const float4*)(Vg + (size_t)(kt*64 + row) * E_DIM + c4);
            uint32_t* vd = &Vs[row * SPAD + c4];
            vd[0] = f2tf(vv.x); vd[1] = f2tf(vv.y); vd[2] = f2tf(vv.z); vd[3] = f2tf(vv.w);
        }
        __syncthreads();

        // ---- S = Q @ K^T : warp computes its 16x64 strip ----
        float sf[8][4];
        #pragma unroll
        for (int nt = 0; nt < 8; nt++)
            #pragma unroll
            for (int e = 0; e < 4; e++) sf[nt][e] = 0.f;

        #pragma unroll
        for (int kk = 0; kk < 8; kk++) {
            uint2 qa = *(const uint2*)&Qs[R0 * SPAD + kk * 8 + 2 * q];  // (a0,a2)
            uint2 qb = *(const uint2*)&Qs[R1 * SPAD + kk * 8 + 2 * q];  // (a1,a3)
            #pragma unroll
            for (int nt = 0; nt < 8; nt++) {
                uint2 kb = *(const uint2*)&Ks[(nt * 8 + r) * SPAD + kk * 8 + 2 * q];
                mma_tf32(sf[nt][0], sf[nt][1], sf[nt][2], sf[nt][3],
                         qa.x, qb.x, qa.y, qb.y, kb.x, kb.y);
            }
        }

        // ---- online softmax, fully in registers (quad shfl reductions) ----
        float mx0 = sf[0][0], mx1 = sf[0][2];
        #pragma unroll
        for (int nt = 0; nt < 8; nt++) {
            mx0 = fmaxf(mx0, fmaxf(sf[nt][0], sf[nt][1]));
            mx1 = fmaxf(mx1, fmaxf(sf[nt][2], sf[nt][3]));
        }
        mx0 = fmaxf(mx0, __shfl_xor_sync(0xffffffffu, mx0, 1));
        mx0 = fmaxf(mx0, __shfl_xor_sync(0xffffffffu, mx0, 2));
        mx1 = fmaxf(mx1, __shfl_xor_sync(0xffffffffu, mx1, 1));
        mx1 = fmaxf(mx1, __shfl_xor_sync(0xffffffffu, mx1, 2));

        float mn0 = fmaxf(m0, mx0), mn1 = fmaxf(m1, mx1);
        float al0 = exp2a(m0 - mn0), al1 = exp2a(m1 - mn1);
        float s0 = 0.f, s1 = 0.f;
        #pragma unroll
        for (int nt = 0; nt < 8; nt++) {
            float p0 = exp2a(sf[nt][0] - mn0); s0 += p0; sf[nt][0] = __uint_as_float(f2tf(p0));
            float p1 = exp2a(sf[nt][1] - mn0); s0 += p1; sf[nt][1] = __uint_as_float(f2tf(p1));
            float p2 = exp2a(sf[nt][2] - mn1); s1 += p2; sf[nt][2] = __uint_as_float(f2tf(p2));
            float p3 = exp2a(sf[nt][3] - mn1); s1 += p3; sf[nt][3] = __uint_as_float(f2tf(p3));
        }
        s0 += __shfl_xor_sync(0xffffffffu, s0, 1);
        s0 += __shfl_xor_sync(0xffffffffu, s0, 2);
        s1 += __shfl_xor_sync(0xffffffffu, s1, 1);
        s1 += __shfl_xor_sync(0xffffffffu, s1, 2);
        l0 = l0 * al0 + s0;  l1 = l1 * al1 + s1;
        m0 = mn0;            m1 = mn1;

        // ---- rescale O accumulators ----
        #pragma unroll
        for (int nt = 0; nt < 8; nt++) {
            of[nt][0] *= al0; of[nt][1] *= al0;
            of[nt][2] *= al1; of[nt][3] *= al1;
        }

        // ---- O += P @ V : P transposed C-layout -> A-layout via quad shfl ----
        #pragma unroll
        for (int kk = 0; kk < 8; kk++) {
            float t00 = __shfl_sync(0xffffffffu, sf[kk][0], srcA);
            float t01 = __shfl_sync(0xffffffffu, sf[kk][1], srcA);
            float t10 = __shfl_sync(0xffffffffu, sf[kk][2], srcA);
            float t11 = __shfl_sync(0xffffffffu, sf[kk][3], srcA);
            float u00 = __shfl_sync(0xffffffffu, sf[kk][0], srcB);
            float u01 = __shfl_sync(0xffffffffu, sf[kk][1], srcB);
            float u10 = __shfl_sync(0xffffffffu, sf[kk][2], srcB);
            float u11 = __shfl_sync(0xffffffffu, sf[kk][3], srcB);
            const bool odd = (q & 1);
            uint32_t a0 = __float_as_uint(odd ? t01 : t00);
            uint32_t a1 = __float_as_uint(odd ? t11 : t10);
            uint32_t a2 = __float_as_uint(odd ? u01 : u00);
            uint32_t a3 = __float_as_uint(odd ? u11 : u10);
            #pragma unroll
            for (int nt = 0; nt < 8; nt++) {
                uint32_t b0 = Vs[(kk * 8 + q) * SPAD + nt * 8 + r];
                uint32_t b1 = Vs[(kk * 8 + 4 + q) * SPAD + nt * 8 + r];
                mma_tf32(of[nt][0], of[nt][1], of[nt][2], of[nt][3],
                         a0, a1, a2, a3, b0, b1);
            }
        }
    }

    // ---- epilogue: divide by l, write [b*S + qrow, h*64 + d] ----
    float* Og = O + ((size_t)b * SEQ + qt * 128) * E_DIM + (size_t)h * HDIM;
    float i0 = 1.f / l0, i1 = 1.f / l1;
    #pragma unroll
    for (int nt = 0; nt < 8; nt++) {
        int cc = nt * 8 + 2 * q;
        *(float2*)(Og + (size_t)R0 * E_DIM + cc) = make_float2(of[nt][0] * i0, of[nt][1] * i0);
        *(float2*)(Og + (size_t)R1 * E_DIM + cc) = make_float2(of[nt][2] * i1, of[nt][3] * i1);
    }
}

// ============================================================================
extern "C" void kernel_launch(void* const* d_in, const int* in_sizes, int n_in,
                              void* d_out, int out_size)
{
    const float* query = (const float*)d_in[0];
    const float* key   = (const float*)d_in[1];
    const float* value = (const float*)d_in[2];
    const float* Wq    = (const float*)d_in[3];
    const float* Wk    = (const float*)d_in[4];
    const float* Wv    = (const float*)d_in[5];
    const float* Wo    = (const float*)d_in[6];
    float* out = (float*)d_out;

    float *gq, *gk, *gv, *ga;
    cudaGetSymbolAddress((void**)&gq, g_q);
    cudaGetSymbolAddress((void**)&gk, g_k);
    cudaGetSymbolAddress((void**)&gv, g_v);
    cudaGetSymbolAddress((void**)&ga, g_attn);

    cudaFuncSetAttribute(flash_attn, cudaFuncAttributeMaxDynamicSharedMemorySize, FLASH_SMEM);

    // fused Q/K/V projections: one launch, z selects the triple
    gemm3<<<dim3(E_DIM / BN, MTOT / BM, 3), 256>>>(query, key, value,
                                                   Wq, Wk, Wv,
                                                   gq, gk, gv);

    flash_attn<<<dim3(SEQ / 128, HEADS, BATCH), 256, FLASH_SMEM>>>(gq, gk, gv, ga);

    // output projection
    gemm3<<<dim3(E_DIM / BN, MTOT / BM, 1), 256>>>(ga, ga, ga,
                                                   Wo, Wo, Wo,
                                                   out, out, out);
}

// round 5
// speedup vs baseline: 3.1918x; 1.9301x over previous
#include <cuda_runtime.h>
#include <cuda_fp16.h>
#include <cstdint>

#define E_DIM 1024
#define HEADS 16
#define HDIM  64
#define SEQ   2048
#define BATCH 4
#define MTOT  (BATCH*SEQ)   // 8192

// ---- scratch (__device__ globals; alloc-free rule) ----
__device__ __half c_q[MTOT*E_DIM];     // fp16 copies of inputs
__device__ __half c_k[MTOT*E_DIM];
__device__ __half c_v[MTOT*E_DIM];
__device__ __half c_wq[E_DIM*E_DIM];
__device__ __half c_wk[E_DIM*E_DIM];
__device__ __half c_wv[E_DIM*E_DIM];
__device__ __half c_wo[E_DIM*E_DIM];
__device__ __half p_q[MTOT*E_DIM];     // projection outputs (q pre-scaled)
__device__ __half p_k[MTOT*E_DIM];
__device__ __half p_v[MTOT*E_DIM];
__device__ __half p_a[MTOT*E_DIM];     // attention output (fp16)

__device__ __forceinline__ float exp2a(float x){
    float r; asm("ex2.approx.f32 %0, %1;" : "=f"(r) : "f"(x)); return r;
}
__device__ __forceinline__ void cpa16(uint32_t dst, const void* src){
    asm volatile("cp.async.cg.shared.global [%0], [%1], 16;" :: "r"(dst), "l"(src));
}
__device__ __forceinline__ void ldm4(uint32_t& r0, uint32_t& r1, uint32_t& r2, uint32_t& r3, uint32_t a){
    asm volatile("ldmatrix.sync.aligned.m8n8.x4.shared.b16 {%0,%1,%2,%3}, [%4];"
                 : "=r"(r0), "=r"(r1), "=r"(r2), "=r"(r3) : "r"(a));
}
__device__ __forceinline__ void ldm4t(uint32_t& r0, uint32_t& r1, uint32_t& r2, uint32_t& r3, uint32_t a){
    asm volatile("ldmatrix.sync.aligned.m8n8.x4.trans.shared.b16 {%0,%1,%2,%3}, [%4];"
                 : "=r"(r0), "=r"(r1), "=r"(r2), "=r"(r3) : "r"(a));
}
__device__ __forceinline__ void mma16816(float& c0, float& c1, float& c2, float& c3,
    uint32_t a0, uint32_t a1, uint32_t a2, uint32_t a3, uint32_t b0, uint32_t b1){
    asm volatile(
        "mma.sync.aligned.m16n8k16.row.col.f32.f16.f16.f32 "
        "{%0,%1,%2,%3},{%4,%5,%6,%7},{%8,%9},{%0,%1,%2,%3};"
        : "+f"(c0), "+f"(c1), "+f"(c2), "+f"(c3)
        : "r"(a0), "r"(a1), "r"(a2), "r"(a3), "r"(b0), "r"(b1));
}
__device__ __forceinline__ uint32_t packh2(float lo, float hi){
    __half2 h = __floats2half2_rn(lo, hi);
    return *reinterpret_cast<uint32_t*>(&h);
}

// ============================================================================
// Conversion pass: fp32 -> fp16 for the 3 activations + 4 weights.
// ============================================================================
__global__ __launch_bounds__(256) void convert_all(
    const float* q, const float* k, const float* v,
    const float* wq, const float* wk, const float* wv, const float* wo)
{
    const float* src; __half* dst; int n;
    switch (blockIdx.y) {
        case 0: src=q;  dst=c_q;  n=MTOT*E_DIM; break;
        case 1: src=k;  dst=c_k;  n=MTOT*E_DIM; break;
        case 2: src=v;  dst=c_v;  n=MTOT*E_DIM; break;
        case 3: src=wq; dst=c_wq; n=E_DIM*E_DIM; break;
        case 4: src=wk; dst=c_wk; n=E_DIM*E_DIM; break;
        case 5: src=wv; dst=c_wv; n=E_DIM*E_DIM; break;
        default:src=wo; dst=c_wo; n=E_DIM*E_DIM; break;
    }
    int i = (blockIdx.x * 256 + threadIdx.x) * 8;
    if (i >= n) return;
    float4 f0 = *(const float4*)(src + i);
    float4 f1 = *(const float4*)(src + i + 4);
    uint4 o;
    o.x = packh2(f0.x, f0.y); o.y = packh2(f0.z, f0.w);
    o.z = packh2(f1.x, f1.y); o.w = packh2(f1.z, f1.w);
    *(uint4*)(dst + i) = o;
}

// ============================================================================
// GEMM: C[M,N] = A[M,K] @ W[N,K]^T, fp16 in, fp32 acc, ldmatrix + cp.async.
// BM=BN=128, BK=32, 256 threads (8 warps: 2 m x 4 n). z selects triple.
// WRITE_F32=0: write half (scale applied for z==0). =1: write float.
// ============================================================================
template<int WRITE_F32>
__global__ __launch_bounds__(256, 2) void gemm_h(
    const __half* A0, const __half* A1, const __half* A2,
    const __half* W0, const __half* W1, const __half* W2,
    void* C0v, void* C1v, void* C2v, float scale0)
{
    __shared__ __half As[2][128][40];
    __shared__ __half Bs[2][128][40];

    const int z = blockIdx.z;
    const __half* A = z==0 ? A0 : (z==1 ? A1 : A2);
    const __half* W = z==0 ? W0 : (z==1 ? W1 : W2);
    void* Cv       = z==0 ? C0v : (z==1 ? C1v : C2v);
    const float scale = (z==0) ? scale0 : 1.f;
    const int Kd = E_DIM, N = E_DIM;

    const int t = threadIdx.x, lane = t & 31, w = t >> 5;
    const int wm = w & 1, wn = w >> 1, gr = lane >> 2, qq = lane & 3;
    const int bm = blockIdx.y * 128, bn = blockIdx.x * 128;

    const int ldrow = t >> 1, hb = (t & 1) * 16;
    const uint32_t sA = (uint32_t)__cvta_generic_to_shared(&As[0][0][0]);
    const uint32_t sB = (uint32_t)__cvta_generic_to_shared(&Bs[0][0][0]);

    auto issue = [&](int k0, int s){
        const __half* ap = A + (size_t)(bm + ldrow) * Kd + k0 + hb;
        const __half* wp = W + (size_t)(bn + ldrow) * Kd + k0 + hb;
        uint32_t da = sA + (uint32_t)(((s*128 + ldrow)*40 + hb) * 2);
        uint32_t db = sB + (uint32_t)(((s*128 + ldrow)*40 + hb) * 2);
        cpa16(da, ap);      cpa16(da + 16, ap + 8);
        cpa16(db, wp);      cpa16(db + 16, wp + 8);
    };

    const int arow = lane & 15;
    const int acs  = (lane & 16) >> 1;               // +8 k-cols for hi lanes
    const int brow = (lane & 7) + ((lane & 16) >> 1);
    const int bcs  = lane & 8;

    float acc[4][4][4];
    #pragma unroll
    for (int i = 0; i < 4; i++)
        #pragma unroll
        for (int j = 0; j < 4; j++)
            #pragma unroll
            for (int e = 0; e < 4; e++) acc[i][j][e] = 0.f;

    issue(0, 0);
    asm volatile("cp.async.commit_group;");

    const int NKI = Kd / 32;   // 32
    for (int ki = 0; ki < NKI; ki++) {
        asm volatile("cp.async.wait_group 0;" ::: "memory");
        __syncthreads();
        if (ki + 1 < NKI) { issue((ki+1)*32, (ki+1)&1); asm volatile("cp.async.commit_group;"); }
        const int s = ki & 1;

        #pragma unroll
        for (int kg = 0; kg < 2; kg++) {
            const int kk = kg * 16;
            uint32_t af[4][4], bf[4][2];
            #pragma unroll
            for (int mt = 0; mt < 4; mt++)
                ldm4(af[mt][0], af[mt][1], af[mt][2], af[mt][3],
                     sA + (uint32_t)((((s*128) + wm*64 + mt*16 + arow)*40 + kk + acs) * 2));
            #pragma unroll
            for (int np = 0; np < 2; np++)
                ldm4(bf[2*np][0], bf[2*np][1], bf[2*np+1][0], bf[2*np+1][1],
                     sB + (uint32_t)((((s*128) + wn*32 + np*16 + brow)*40 + kk + bcs) * 2));
            #pragma unroll
            for (int mt = 0; mt < 4; mt++)
                #pragma unroll
                for (int nt = 0; nt < 4; nt++)
                    mma16816(acc[mt][nt][0], acc[mt][nt][1], acc[mt][nt][2], acc[mt][nt][3],
                             af[mt][0], af[mt][1], af[mt][2], af[mt][3],
                             bf[nt][0], bf[nt][1]);
        }
        __syncthreads();
    }

    if (WRITE_F32) {
        float* C = (float*)Cv;
        #pragma unroll
        for (int mt = 0; mt < 4; mt++) {
            int r0 = bm + wm*64 + mt*16 + gr;
            #pragma unroll
            for (int nt = 0; nt < 4; nt++) {
                int cc = bn + wn*32 + nt*8 + qq*2;
                *(float2*)(C + (size_t)r0 * N + cc)     = make_float2(acc[mt][nt][0], acc[mt][nt][1]);
                *(float2*)(C + (size_t)(r0+8) * N + cc) = make_float2(acc[mt][nt][2], acc[mt][nt][3]);
            }
        }
    } else {
        __half* C = (__half*)Cv;
        #pragma unroll
        for (int mt = 0; mt < 4; mt++) {
            int r0 = bm + wm*64 + mt*16 + gr;
            #pragma unroll
            for (int nt = 0; nt < 4; nt++) {
                int cc = bn + wn*32 + nt*8 + qq*2;
                *(uint32_t*)(C + (size_t)r0 * N + cc)     = packh2(acc[mt][nt][0]*scale, acc[mt][nt][1]*scale);
                *(uint32_t*)(C + (size_t)(r0+8) * N + cc) = packh2(acc[mt][nt][2]*scale, acc[mt][nt][3]*scale);
            }
        }
    }
}

// ============================================================================
// Flash attention fp16: Br=128, Bc=64. 8 warps, warp w owns rows [16w,16w+16).
// cp.async double-buffered K/V, Q fragments hoisted to registers, ldmatrix
// everywhere, register-only softmax, zero-shuffle P repack (k16 frag trick).
// Rows padded to 72 halves (144B) -> conflict-free ldmatrix.
// ============================================================================
#define FSM ((128 + 4*64) * 72 * 2)   // 55296 bytes

__global__ __launch_bounds__(256, 2) void flash_h(
    const __half* __restrict__ Q, const __half* __restrict__ K,
    const __half* __restrict__ V, __half* __restrict__ O)
{
    extern __shared__ __half sh[];
    __half* Qs = sh;                   // [128][72]
    __half* Ks = sh + 128*72;          // [2][64][72]
    __half* Vs = Ks + 2*64*72;         // [2][64][72]
    const uint32_t sQ = (uint32_t)__cvta_generic_to_shared(Qs);
    const uint32_t sK = (uint32_t)__cvta_generic_to_shared(Ks);
    const uint32_t sV = (uint32_t)__cvta_generic_to_shared(Vs);

    const int t = threadIdx.x, lane = t & 31, w = t >> 5;
    const int gr = lane >> 2, qq = lane & 3;
    const int qt = blockIdx.x, h = blockIdx.y, b = blockIdx.z;

    const __half* Qg = Q + ((size_t)b*SEQ + qt*128) * E_DIM + h*HDIM;
    const __half* Kg = K + (size_t)b*SEQ*E_DIM + h*HDIM;
    const __half* Vg = V + (size_t)b*SEQ*E_DIM + h*HDIM;

    // ---- issue Q copy + first K/V tile ----
    {
        int row = t >> 1, hoff = (t & 1) * 32;
        const __half* qp = Qg + (size_t)row * E_DIM + hoff;
        uint32_t d = sQ + (uint32_t)((row*72 + hoff) * 2);
        cpa16(d, qp); cpa16(d+16, qp+8); cpa16(d+32, qp+16); cpa16(d+48, qp+24);
    }
    const int kvrow = t >> 2, kvh = (t & 3) * 16;
    auto issueKV = [&](int kt, int s){
        const __half* kp = Kg + (size_t)(kt*64 + kvrow) * E_DIM + kvh;
        const __half* vp = Vg + (size_t)(kt*64 + kvrow) * E_DIM + kvh;
        uint32_t dk = sK + (uint32_t)(((s*64 + kvrow)*72 + kvh) * 2);
        uint32_t dv = sV + (uint32_t)(((s*64 + kvrow)*72 + kvh) * 2);
        cpa16(dk, kp); cpa16(dk+16, kp+8);
        cpa16(dv, vp); cpa16(dv+16, vp+8);
    };
    issueKV(0, 0);
    asm volatile("cp.async.commit_group;");

    const int aro = w*16 + (lane & 15);
    const int acs = (lane & 16) >> 1;
    const int bro = (lane & 7) + ((lane & 16) >> 1);
    const int bcs = lane & 8;
    const int vro = (lane & 7) + (lane & 8);
    const int vcs = (lane & 16) >> 1;

    uint32_t qf[4][4];
    float of[8][4];
    #pragma unroll
    for (int nt = 0; nt < 8; nt++)
        #pragma unroll
        for (int e = 0; e < 4; e++) of[nt][e] = 0.f;
    float m0 = -1e30f, m1 = -1e30f, l0 = 0.f, l1 = 0.f;

    const int NT = SEQ / 64;   // 32
    for (int kt = 0; kt < NT; kt++) {
        asm volatile("cp.async.wait_group 0;" ::: "memory");
        __syncthreads();
        if (kt == 0) {
            #pragma unroll
            for (int g = 0; g < 4; g++)
                ldm4(qf[g][0], qf[g][1], qf[g][2], qf[g][3],
                     sQ + (uint32_t)((aro*72 + g*16 + acs) * 2));
        }
        if (kt + 1 < NT) { issueKV(kt+1, (kt+1)&1); asm volatile("cp.async.commit_group;"); }
        const int s = kt & 1;

        // ---- S = Q @ K^T (warp: 16x64) ----
        float sf[8][4];
        #pragma unroll
        for (int nt = 0; nt < 8; nt++)
            #pragma unroll
            for (int e = 0; e < 4; e++) sf[nt][e] = 0.f;

        #pragma unroll
        for (int g = 0; g < 4; g++) {
            #pragma unroll
            for (int np = 0; np < 4; np++) {
                uint32_t b0, b1, b2, b3;
                ldm4(b0, b1, b2, b3,
                     sK + (uint32_t)(((s*64 + np*16 + bro)*72 + g*16 + bcs) * 2));
                mma16816(sf[2*np][0], sf[2*np][1], sf[2*np][2], sf[2*np][3],
                         qf[g][0], qf[g][1], qf[g][2], qf[g][3], b0, b1);
                mma16816(sf[2*np+1][0], sf[2*np+1][1], sf[2*np+1][2], sf[2*np+1][3],
                         qf[g][0], qf[g][1], qf[g][2], qf[g][3], b2, b3);
            }
        }

        // ---- online softmax (registers + quad shfl; scores are log2-scaled) ----
        float mx0 = sf[0][0], mx1 = sf[0][2];
        #pragma unroll
        for (int nt = 0; nt < 8; nt++) {
            mx0 = fmaxf(mx0, fmaxf(sf[nt][0], sf[nt][1]));
            mx1 = fmaxf(mx1, fmaxf(sf[nt][2], sf[nt][3]));
        }
        mx0 = fmaxf(mx0, __shfl_xor_sync(0xffffffffu, mx0, 1));
        mx0 = fmaxf(mx0, __shfl_xor_sync(0xffffffffu, mx0, 2));
        mx1 = fmaxf(mx1, __shfl_xor_sync(0xffffffffu, mx1, 1));
        mx1 = fmaxf(mx1, __shfl_xor_sync(0xffffffffu, mx1, 2));

        float mn0 = fmaxf(m0, mx0), mn1 = fmaxf(m1, mx1);
        float al0 = exp2a(m0 - mn0), al1 = exp2a(m1 - mn1);
        float s0 = 0.f, s1 = 0.f;
        #pragma unroll
        for (int nt = 0; nt < 8; nt++) {
            sf[nt][0] = exp2a(sf[nt][0] - mn0); s0 += sf[nt][0];
            sf[nt][1] = exp2a(sf[nt][1] - mn0); s0 += sf[nt][1];
            sf[nt][2] = exp2a(sf[nt][2] - mn1); s1 += sf[nt][2];
            sf[nt][3] = exp2a(sf[nt][3] - mn1); s1 += sf[nt][3];
        }
        s0 += __shfl_xor_sync(0xffffffffu, s0, 1);
        s0 += __shfl_xor_sync(0xffffffffu, s0, 2);
        s1 += __shfl_xor_sync(0xffffffffu, s1, 1);
        s1 += __shfl_xor_sync(0xffffffffu, s1, 2);
        l0 = l0 * al0 + s0;  l1 = l1 * al1 + s1;
        m0 = mn0;            m1 = mn1;

        // ---- P repack: C-frag fp32 -> A-frag fp16 (pure register cvt) ----
        uint32_t pa[4][4];
        #pragma unroll
        for (int g = 0; g < 4; g++) {
            pa[g][0] = packh2(sf[2*g][0],   sf[2*g][1]);
            pa[g][1] = packh2(sf[2*g][2],   sf[2*g][3]);
            pa[g][2] = packh2(sf[2*g+1][0], sf[2*g+1][1]);
            pa[g][3] = packh2(sf[2*g+1][2], sf[2*g+1][3]);
        }

        // ---- rescale O, then O += P @ V ----
        #pragma unroll
        for (int nt = 0; nt < 8; nt++) {
            of[nt][0] *= al0; of[nt][1] *= al0;
            of[nt][2] *= al1; of[nt][3] *= al1;
        }
        #pragma unroll
        for (int g = 0; g < 4; g++) {
            #pragma unroll
            for (int np = 0; np < 4; np++) {
                uint32_t b0, b1, b2, b3;
                ldm4t(b0, b1, b2, b3,
                      sV + (uint32_t)(((s*64 + g*16 + vro)*72 + np*16 + vcs) * 2));
                mma16816(of[2*np][0], of[2*np][1], of[2*np][2], of[2*np][3],
                         pa[g][0], pa[g][1], pa[g][2], pa[g][3], b0, b1);
                mma16816(of[2*np+1][0], of[2*np+1][1], of[2*np+1][2], of[2*np+1][3],
                         pa[g][0], pa[g][1], pa[g][2], pa[g][3], b2, b3);
            }
        }
    }

    // ---- epilogue: O /= l, write fp16 ----
    __half* Og = O + ((size_t)b*SEQ + qt*128) * E_DIM + h*HDIM;
    const int R0 = w*16 + gr, R1 = R0 + 8;
    float i0 = 1.f / l0, i1 = 1.f / l1;
    #pragma unroll
    for (int nt = 0; nt < 8; nt++) {
        int cc = nt*8 + 2*qq;
        *(uint32_t*)(Og + (size_t)R0 * E_DIM + cc) = packh2(of[nt][0]*i0, of[nt][1]*i0);
        *(uint32_t*)(Og + (size_t)R1 * E_DIM + cc) = packh2(of[nt][2]*i1, of[nt][3]*i1);
    }
}

// ============================================================================
extern "C" void kernel_launch(void* const* d_in, const int* in_sizes, int n_in,
                              void* d_out, int out_size)
{
    const float* query = (const float*)d_in[0];
    const float* key   = (const float*)d_in[1];
    const float* value = (const float*)d_in[2];
    const float* Wq    = (const float*)d_in[3];
    const float* Wk    = (const float*)d_in[4];
    const float* Wv    = (const float*)d_in[5];
    const float* Wo    = (const float*)d_in[6];
    float* out = (float*)d_out;

    __half *cq, *ck, *cv, *cwq, *cwk, *cwv, *cwo, *pq, *pk, *pv, *pa;
    cudaGetSymbolAddress((void**)&cq,  c_q);
    cudaGetSymbolAddress((void**)&ck,  c_k);
    cudaGetSymbolAddress((void**)&cv,  c_v);
    cudaGetSymbolAddress((void**)&cwq, c_wq);
    cudaGetSymbolAddress((void**)&cwk, c_wk);
    cudaGetSymbolAddress((void**)&cwv, c_wv);
    cudaGetSymbolAddress((void**)&cwo, c_wo);
    cudaGetSymbolAddress((void**)&pq,  p_q);
    cudaGetSymbolAddress((void**)&pk,  p_k);
    cudaGetSymbolAddress((void**)&pv,  p_v);
    cudaGetSymbolAddress((void**)&pa,  p_a);

    cudaFuncSetAttribute(flash_h, cudaFuncAttributeMaxDynamicSharedMemorySize, FSM);

    const float qscale = 0.125f * 1.4426950408889634f;   // 1/sqrt(64) * log2(e)

    convert_all<<<dim3(MTOT*E_DIM/2048, 7), 256>>>(query, key, value, Wq, Wk, Wv, Wo);

    gemm_h<0><<<dim3(8, 64, 3), 256>>>(cq, ck, cv, cwq, cwk, cwv, pq, pk, pv, qscale);

    flash_h<<<dim3(SEQ/128, HEADS, BATCH), 256, FSM>>>(pq, pk, pv, pa);

    gemm_h<1><<<dim3(8, 64, 1), 256>>>(pa, pa, pa, cwo, cwo, cwo, out, out, out, 1.f);
}

// round 7
// speedup vs baseline: 3.2790x; 1.0273x over previous
#include <cuda_runtime.h>
#include <cuda_fp16.h>
#include <cstdint>

#define E_DIM 1024
#define HEADS 16
#define HDIM  64
#define SEQ   2048
#define BATCH 4
#define MTOT  (BATCH*SEQ)   // 8192

// ---- scratch (__device__ globals; alloc-free rule) ----
__device__ __half c_q[MTOT*E_DIM];     // fp16 copies of inputs
__device__ __half c_k[MTOT*E_DIM];
__device__ __half c_v[MTOT*E_DIM];
__device__ __half c_wq[E_DIM*E_DIM];
__device__ __half c_wk[E_DIM*E_DIM];
__device__ __half c_wv[E_DIM*E_DIM];
__device__ __half c_wo[E_DIM*E_DIM];
__device__ __half p_q[MTOT*E_DIM];     // projection outputs (q pre-scaled)
__device__ __half p_k[MTOT*E_DIM];
__device__ __half p_v[MTOT*E_DIM];
__device__ __half p_a[MTOT*E_DIM];     // attention output (fp16)

__device__ __forceinline__ float exp2a(float x){
    float r; asm("ex2.approx.f32 %0, %1;" : "=f"(r) : "f"(x)); return r;
}
__device__ __forceinline__ void cpa16(uint32_t dst, const void* src){
    asm volatile("cp.async.cg.shared.global [%0], [%1], 16;" :: "r"(dst), "l"(src));
}
__device__ __forceinline__ void ldm4(uint32_t& r0, uint32_t& r1, uint32_t& r2, uint32_t& r3, uint32_t a){
    asm volatile("ldmatrix.sync.aligned.m8n8.x4.shared.b16 {%0,%1,%2,%3}, [%4];"
                 : "=r"(r0), "=r"(r1), "=r"(r2), "=r"(r3) : "r"(a));
}
__device__ __forceinline__ void ldm4t(uint32_t& r0, uint32_t& r1, uint32_t& r2, uint32_t& r3, uint32_t a){
    asm volatile("ldmatrix.sync.aligned.m8n8.x4.trans.shared.b16 {%0,%1,%2,%3}, [%4];"
                 : "=r"(r0), "=r"(r1), "=r"(r2), "=r"(r3) : "r"(a));
}
__device__ __forceinline__ void mma16816(float& c0, float& c1, float& c2, float& c3,
    uint32_t a0, uint32_t a1, uint32_t a2, uint32_t a3, uint32_t b0, uint32_t b1){
    asm volatile(
        "mma.sync.aligned.m16n8k16.row.col.f32.f16.f16.f32 "
        "{%0,%1,%2,%3},{%4,%5,%6,%7},{%8,%9},{%0,%1,%2,%3};"
        : "+f"(c0), "+f"(c1), "+f"(c2), "+f"(c3)
        : "r"(a0), "r"(a1), "r"(a2), "r"(a3), "r"(b0), "r"(b1));
}
__device__ __forceinline__ uint32_t packh2(float lo, float hi){
    __half2 h = __floats2half2_rn(lo, hi);
    return *reinterpret_cast<uint32_t*>(&h);
}

// ============================================================================
// Conversion pass: fp32 -> fp16 for the 3 activations + 4 weights.
// ============================================================================
__global__ __launch_bounds__(256) void convert_all(
    const float* q, const float* k, const float* v,
    const float* wq, const float* wk, const float* wv, const float* wo)
{
    const float* src; __half* dst; int n;
    switch (blockIdx.y) {
        case 0: src=q;  dst=c_q;  n=MTOT*E_DIM; break;
        case 1: src=k;  dst=c_k;  n=MTOT*E_DIM; break;
        case 2: src=v;  dst=c_v;  n=MTOT*E_DIM; break;
        case 3: src=wq; dst=c_wq; n=E_DIM*E_DIM; break;
        case 4: src=wk; dst=c_wk; n=E_DIM*E_DIM; break;
        case 5: src=wv; dst=c_wv; n=E_DIM*E_DIM; break;
        default:src=wo; dst=c_wo; n=E_DIM*E_DIM; break;
    }
    int i = (blockIdx.x * 256 + threadIdx.x) * 8;
    if (i >= n) return;
    float4 f0 = *(const float4*)(src + i);
    float4 f1 = *(const float4*)(src + i + 4);
    uint4 o;
    o.x = packh2(f0.x, f0.y); o.y = packh2(f0.z, f0.w);
    o.z = packh2(f1.x, f1.y); o.w = packh2(f1.z, f1.w);
    *(uint4*)(dst + i) = o;
}

// ============================================================================
// GEMM: C[M,N] = A[M,K] @ W[N,K]^T, fp16 in, fp32 acc, ldmatrix + cp.async.
// BM=BN=128, BK=32, 256 threads (8 warps: 2m x 4n). 4-stage cp.async ring,
// ONE __syncthreads per K-iter, commit every iter => wait_group 2 is exact.
// z selects among 3 (A,W,C) triples. WRITE_F32: out dtype.
// ============================================================================
#define GS 4
#define GNK (E_DIM/32)    // 32

template<int WRITE_F32>
__global__ __launch_bounds__(256, 2) void gemm_h(
    const __half* A0, const __half* A1, const __half* A2,
    const __half* W0, const __half* W1, const __half* W2,
    void* C0v, void* C1v, void* C2v, float scale0)
{
    __shared__ __half As[GS][128][40];
    __shared__ __half Bs[GS][128][40];

    const int z = blockIdx.z;
    const __half* A = z==0 ? A0 : (z==1 ? A1 : A2);
    const __half* W = z==0 ? W0 : (z==1 ? W1 : W2);
    void* Cv       = z==0 ? C0v : (z==1 ? C1v : C2v);
    const float scale = (z==0) ? scale0 : 1.f;
    const int Kd = E_DIM, N = E_DIM;

    const int t = threadIdx.x, lane = t & 31, w = t >> 5;
    const int wm = w & 1, wn = w >> 1, gr = lane >> 2, qq = lane & 3;
    const int bm = blockIdx.y * 128, bn = blockIdx.x * 128;

    const int ldrow = t >> 1, hb = (t & 1) * 16;
    const uint32_t sA = (uint32_t)__cvta_generic_to_shared(&As[0][0][0]);
    const uint32_t sB = (uint32_t)__cvta_generic_to_shared(&Bs[0][0][0]);

    auto issue = [&](int k0, int s){
        const __half* ap = A + (size_t)(bm + ldrow) * Kd + k0 + hb;
        const __half* wp = W + (size_t)(bn + ldrow) * Kd + k0 + hb;
        uint32_t da = sA + (uint32_t)(((s*128 + ldrow)*40 + hb) * 2);
        uint32_t db = sB + (uint32_t)(((s*128 + ldrow)*40 + hb) * 2);
        cpa16(da, ap);      cpa16(da + 16, ap + 8);
        cpa16(db, wp);      cpa16(db + 16, wp + 8);
    };

    const int arow = lane & 15;
    const int acs  = (lane & 16) >> 1;
    const int brow = (lane & 7) + ((lane & 16) >> 1);
    const int bcs  = lane & 8;

    float acc[4][4][4];
    #pragma unroll
    for (int i = 0; i < 4; i++)
        #pragma unroll
        for (int j = 0; j < 4; j++)
            #pragma unroll
            for (int e = 0; e < 4; e++) acc[i][j][e] = 0.f;

    // prologue: stages 0..2
    issue(0, 0);  asm volatile("cp.async.commit_group;");
    issue(32, 1); asm volatile("cp.async.commit_group;");
    issue(64, 2); asm volatile("cp.async.commit_group;");

    for (int c = 0; c < GNK; c++) {
        asm volatile("cp.async.wait_group 2;" ::: "memory");
        __syncthreads();
        if (c + 3 < GNK) issue((c + 3) * 32, (c + 3) & (GS - 1));
        asm volatile("cp.async.commit_group;");
        const int s = c & (GS - 1);

        #pragma unroll
        for (int kg = 0; kg < 2; kg++) {
            const int kk = kg * 16;
            uint32_t af[4][4], bf[4][2];
            #pragma unroll
            for (int mt = 0; mt < 4; mt++)
                ldm4(af[mt][0], af[mt][1], af[mt][2], af[mt][3],
                     sA + (uint32_t)((((s*128) + wm*64 + mt*16 + arow)*40 + kk + acs) * 2));
            #pragma unroll
            for (int np = 0; np < 2; np++)
                ldm4(bf[2*np][0], bf[2*np][1], bf[2*np+1][0], bf[2*np+1][1],
                     sB + (uint32_t)((((s*128) + wn*32 + np*16 + brow)*40 + kk + bcs) * 2));
            #pragma unroll
            for (int mt = 0; mt < 4; mt++)
                #pragma unroll
                for (int nt = 0; nt < 4; nt++)
                    mma16816(acc[mt][nt][0], acc[mt][nt][1], acc[mt][nt][2], acc[mt][nt][3],
                             af[mt][0], af[mt][1], af[mt][2], af[mt][3],
                             bf[nt][0], bf[nt][1]);
        }
    }

    if (WRITE_F32) {
        float* C = (float*)Cv;
        #pragma unroll
        for (int mt = 0; mt < 4; mt++) {
            int r0 = bm + wm*64 + mt*16 + gr;
            #pragma unroll
            for (int nt = 0; nt < 4; nt++) {
                int cc = bn + wn*32 + nt*8 + qq*2;
                *(float2*)(C + (size_t)r0 * N + cc)     = make_float2(acc[mt][nt][0], acc[mt][nt][1]);
                *(float2*)(C + (size_t)(r0+8) * N + cc) = make_float2(acc[mt][nt][2], acc[mt][nt][3]);
            }
        }
    } else {
        __half* C = (__half*)Cv;
        #pragma unroll
        for (int mt = 0; mt < 4; mt++) {
            int r0 = bm + wm*64 + mt*16 + gr;
            #pragma unroll
            for (int nt = 0; nt < 4; nt++) {
                int cc = bn + wn*32 + nt*8 + qq*2;
                *(uint32_t*)(C + (size_t)r0 * N + cc)     = packh2(acc[mt][nt][0]*scale, acc[mt][nt][1]*scale);
                *(uint32_t*)(C + (size_t)(r0+8) * N + cc) = packh2(acc[mt][nt][2]*scale, acc[mt][nt][3]*scale);
            }
        }
    }
}

// ============================================================================
// Flash attention fp16: Br=128, Bc=64. 8 warps, warp w owns rows [16w,16w+16).
// 3-stage cp.async K/V ring (wait_group 1, commit every iter), Q rides group 0.
// ldmatrix everywhere, register-only softmax, zero-shuffle P repack.
// ============================================================================
#define FST 3
#define FSM ((128 + 2*FST*64) * 72 * 2)   // 73728 bytes

__global__ __launch_bounds__(256, 2) void flash_h(
    const __half* __restrict__ Q, const __half* __restrict__ K,
    const __half* __restrict__ V, __half* __restrict__ O)
{
    extern __shared__ __half sh[];
    __half* Qs = sh;                    // [128][72]
    __half* Ks = sh + 128*72;           // [FST][64][72]
    __half* Vs = Ks + FST*64*72;        // [FST][64][72]
    const uint32_t sQ = (uint32_t)__cvta_generic_to_shared(Qs);
    const uint32_t sK = (uint32_t)__cvta_generic_to_shared(Ks);
    const uint32_t sV = (uint32_t)__cvta_generic_to_shared(Vs);

    const int t = threadIdx.x, lane = t & 31, w = t >> 5;
    const int gr = lane >> 2, qq = lane & 3;
    const int qt = blockIdx.x, h = blockIdx.y, b = blockIdx.z;

    const __half* Qg = Q + ((size_t)b*SEQ + qt*128) * E_DIM + h*HDIM;
    const __half* Kg = K + (size_t)b*SEQ*E_DIM + h*HDIM;
    const __half* Vg = V + (size_t)b*SEQ*E_DIM + h*HDIM;

    // ---- Q copy (rides in group 0) ----
    {
        int row = t >> 1, hoff = (t & 1) * 32;
        const __half* qp = Qg + (size_t)row * E_DIM + hoff;
        uint32_t d = sQ + (uint32_t)((row*72 + hoff) * 2);
        cpa16(d, qp); cpa16(d+16, qp+8); cpa16(d+32, qp+16); cpa16(d+48, qp+24);
    }
    const int kvrow = t >> 2, kvh = (t & 3) * 16;
    auto issueKV = [&](int kt, int s){
        const __half* kp = Kg + (size_t)(kt*64 + kvrow) * E_DIM + kvh;
        const __half* vp = Vg + (size_t)(kt*64 + kvrow) * E_DIM + kvh;
        uint32_t dk = sK + (uint32_t)(((s*64 + kvrow)*72 + kvh) * 2);
        uint32_t dv = sV + (uint32_t)(((s*64 + kvrow)*72 + kvh) * 2);
        cpa16(dk, kp); cpa16(dk+16, kp+8);
        cpa16(dv, vp); cpa16(dv+16, vp+8);
    };
    // prologue: chunks 0,1
    issueKV(0, 0); asm volatile("cp.async.commit_group;");
    issueKV(1, 1); asm volatile("cp.async.commit_group;");

    const int aro = w*16 + (lane & 15);
    const int acs = (lane & 16) >> 1;
    const int bro = (lane & 7) + ((lane & 16) >> 1);
    const int bcs = lane & 8;
    const int vro = (lane & 7) + (lane & 8);
    const int vcs = (lane & 16) >> 1;

    uint32_t qf[4][4];
    float of[8][4];
    #pragma unroll
    for (int nt = 0; nt < 8; nt++)
        #pragma unroll
        for (int e = 0; e < 4; e++) of[nt][e] = 0.f;
    float m0 = -1e30f, m1 = -1e30f, l0 = 0.f, l1 = 0.f;

    const int NT = SEQ / 64;   // 32
    for (int kt = 0; kt < NT; kt++) {
        asm volatile("cp.async.wait_group 1;" ::: "memory");
        __syncthreads();
        if (kt == 0) {
            #pragma unroll
            for (int g = 0; g < 4; g++)
                ldm4(qf[g][0], qf[g][1], qf[g][2], qf[g][3],
                     sQ + (uint32_t)((aro*72 + g*16 + acs) * 2));
        }
        if (kt + 2 < NT) issueKV(kt + 2, (kt + 2) % FST);
        asm volatile("cp.async.commit_group;");
        const int s = kt % FST;

        // ---- S = Q @ K^T (warp: 16x64) ----
        float sf[8][4];
        #pragma unroll
        for (int nt = 0; nt < 8; nt++)
            #pragma unroll
            for (int e = 0; e < 4; e++) sf[nt][e] = 0.f;

        #pragma unroll
        for (int g = 0; g < 4; g++) {
            #pragma unroll
            for (int np = 0; np < 4; np++) {
                uint32_t b0, b1, b2, b3;
                ldm4(b0, b1, b2, b3,
                     sK + (uint32_t)(((s*64 + np*16 + bro)*72 + g*16 + bcs) * 2));
                mma16816(sf[2*np][0], sf[2*np][1], sf[2*np][2], sf[2*np][3],
                         qf[g][0], qf[g][1], qf[g][2], qf[g][3], b0, b1);
                mma16816(sf[2*np+1][0], sf[2*np+1][1], sf[2*np+1][2], sf[2*np+1][3],
                         qf[g][0], qf[g][1], qf[g][2], qf[g][3], b2, b3);
            }
        }

        // ---- online softmax (registers + quad shfl; log2-scaled scores) ----
        float mx0 = sf[0][0], mx1 = sf[0][2];
        #pragma unroll
        for (int nt = 0; nt < 8; nt++) {
            mx0 = fmaxf(mx0, fmaxf(sf[nt][0], sf[nt][1]));
            mx1 = fmaxf(mx1, fmaxf(sf[nt][2], sf[nt][3]));
        }
        mx0 = fmaxf(mx0, __shfl_xor_sync(0xffffffffu, mx0, 1));
        mx0 = fmaxf(mx0, __shfl_xor_sync(0xffffffffu, mx0, 2));
        mx1 = fmaxf(mx1, __shfl_xor_sync(0xffffffffu, mx1, 1));
        mx1 = fmaxf(mx1, __shfl_xor_sync(0xffffffffu, mx1, 2));

        float mn0 = fmaxf(m0, mx0), mn1 = fmaxf(m1, mx1);
        float al0 = exp2a(m0 - mn0), al1 = exp2a(m1 - mn1);
        float s0 = 0.f, s1 = 0.f;
        #pragma unroll
        for (int nt = 0; nt < 8; nt++) {
            sf[nt][0] = exp2a(sf[nt][0] - mn0); s0 += sf[nt][0];
            sf[nt][1] = exp2a(sf[nt][1] - mn0); s0 += sf[nt][1];
            sf[nt][2] = exp2a(sf[nt][2] - mn1); s1 += sf[nt][2];
            sf[nt][3] = exp2a(sf[nt][3] - mn1); s1 += sf[nt][3];
        }
        s0 += __shfl_xor_sync(0xffffffffu, s0, 1);
        s0 += __shfl_xor_sync(0xffffffffu, s0, 2);
        s1 += __shfl_xor_sync(0xffffffffu, s1, 1);
        s1 += __shfl_xor_sync(0xffffffffu, s1, 2);
        l0 = l0 * al0 + s0;  l1 = l1 * al1 + s1;
        m0 = mn0;            m1 = mn1;

        // ---- P repack: C-frag fp32 -> A-frag fp16 (pure register cvt) ----
        uint32_t pa[4][4];
        #pragma unroll
        for (int g = 0; g < 4; g++) {
            pa[g][0] = packh2(sf[2*g][0],   sf[2*g][1]);
            pa[g][1] = packh2(sf[2*g][2],   sf[2*g][3]);
            pa[g][2] = packh2(sf[2*g+1][0], sf[2*g+1][1]);
            pa[g][3] = packh2(sf[2*g+1][2], sf[2*g+1][3]);
        }

        // ---- rescale O, then O += P @ V ----
        #pragma unroll
        for (int nt = 0; nt < 8; nt++) {
            of[nt][0] *= al0; of[nt][1] *= al0;
            of[nt][2] *= al1; of[nt][3] *= al1;
        }
        #pragma unroll
        for (int g = 0; g < 4; g++) {
            #pragma unroll
            for (int np = 0; np < 4; np++) {
                uint32_t b0, b1, b2, b3;
                ldm4t(b0, b1, b2, b3,
                      sV + (uint32_t)(((s*64 + g*16 + vro)*72 + np*16 + vcs) * 2));
                mma16816(of[2*np][0], of[2*np][1], of[2*np][2], of[2*np][3],
                         pa[g][0], pa[g][1], pa[g][2], pa[g][3], b0, b1);
                mma16816(of[2*np+1][0], of[2*np+1][1], of[2*np+1][2], of[2*np+1][3],
                         pa[g][0], pa[g][1], pa[g][2], pa[g][3], b2, b3);
            }
        }
    }

    // ---- epilogue: O /= l, write fp16 ----
    __half* Og = O + ((size_t)b*SEQ + qt*128) * E_DIM + h*HDIM;
    const int R0 = w*16 + gr, R1 = R0 + 8;
    float i0 = 1.f / l0, i1 = 1.f / l1;
    #pragma unroll
    for (int nt = 0; nt < 8; nt++) {
        int cc = nt*8 + 2*qq;
        *(uint32_t*)(Og + (size_t)R0 * E_DIM + cc) = packh2(of[nt][0]*i0, of[nt][1]*i0);
        *(uint32_t*)(Og + (size_t)R1 * E_DIM + cc) = packh2(of[nt][2]*i1, of[nt][3]*i1);
    }
}

// ============================================================================
extern "C" void kernel_launch(void* const* d_in, const int* in_sizes, int n_in,
                              void* d_out, int out_size)
{
    const float* query = (const float*)d_in[0];
    const float* key   = (const float*)d_in[1];
    const float* value = (const float*)d_in[2];
    const float* Wq    = (const float*)d_in[3];
    const float* Wk    = (const float*)d_in[4];
    const float* Wv    = (const float*)d_in[5];
    const float* Wo    = (const float*)d_in[6];
    float* out = (float*)d_out;

    __half *cq, *ck, *cv, *cwq, *cwk, *cwv, *cwo, *pq, *pk, *pv, *pa;
    cudaGetSymbolAddress((void**)&cq,  c_q);
    cudaGetSymbolAddress((void**)&ck,  c_k);
    cudaGetSymbolAddress((void**)&cv,  c_v);
    cudaGetSymbolAddress((void**)&cwq, c_wq);
    cudaGetSymbolAddress((void**)&cwk, c_wk);
    cudaGetSymbolAddress((void**)&cwv, c_wv);
    cudaGetSymbolAddress((void**)&cwo, c_wo);
    cudaGetSymbolAddress((void**)&pq,  p_q);
    cudaGetSymbolAddress((void**)&pk,  p_k);
    cudaGetSymbolAddress((void**)&pv,  p_v);
    cudaGetSymbolAddress((void**)&pa,  p_a);

    cudaFuncSetAttribute(flash_h, cudaFuncAttributeMaxDynamicSharedMemorySize, FSM);

    const float qscale = 0.125f * 1.4426950408889634f;   // 1/sqrt(64) * log2(e)

    convert_all<<<dim3(MTOT*E_DIM/2048, 7), 256>>>(query, key, value, Wq, Wk, Wv, Wo);

    gemm_h<0><<<dim3(8, 64, 3), 256>>>(cq, ck, cv, cwq, cwk, cwv, pq, pk, pv, qscale);

    flash_h<<<dim3(SEQ/128, HEADS, BATCH), 256, FSM>>>(pq, pk, pv, pa);

    gemm_h<1><<<dim3(8, 64, 1), 256>>>(pa, pa, pa, cwo, cwo, cwo, out, out, out, 1.f);
}